// round 15
// baseline (speedup 1.0000x reference)
#include <cuda_runtime.h>
#include <cuda_bf16.h>

#define BB 8
#define SS 2048
#define EE 1024
#define HH 128

typedef unsigned int u32;

// ---------------- device scratch ----------------
__device__ __nv_bfloat16 g_wth[3][HH*EE], g_wtl[3][HH*EE];   // W^T split [h][e]
__device__ __nv_bfloat16 g_qh[BB*SS*HH], g_ql[BB*SS*HH];     // Q [s][h]
__device__ __nv_bfloat16 g_kh[BB*SS*HH];                     // K hi [s][h]
__device__ __nv_bfloat16 g_vth[BB*HH*SS], g_vtl[BB*HH*SS];   // V^T [b][h][s]

// ---------------- helpers ----------------
__device__ __forceinline__ u32 smem_u32(const void* p) {
    u32 a;
    asm("{ .reg .u64 t; cvta.to.shared.u64 t, %1; cvt.u32.u64 %0, t; }" : "=r"(a) : "l"(p));
    return a;
}
__device__ __forceinline__ void cpa16(u32 dst, const void* src) {
    asm volatile("cp.async.cg.shared.global [%0], [%1], 16;" :: "r"(dst), "l"(src));
}
#define CP_COMMIT() asm volatile("cp.async.commit_group;" ::: "memory")
#define CP_WAIT(n)  asm volatile("cp.async.wait_group %0;" :: "n"(n) : "memory")

__device__ __forceinline__ u32 packbf(float lo, float hi) {
    u32 r;
    asm("cvt.rn.bf16x2.f32 %0, %1, %2;" : "=r"(r) : "f"(hi), "f"(lo));
    return r;
}
__device__ __forceinline__ u32 packlo(float p0, float p1, u32 h) {
    float r0 = p0 - __uint_as_float(h << 16);
    float r1 = p1 - __uint_as_float(h & 0xffff0000u);
    return packbf(r0, r1);
}
__device__ __forceinline__ void mma16816(float* c, u32 a0, u32 a1, u32 a2, u32 a3,
                                         u32 b0, u32 b1) {
    asm volatile("mma.sync.aligned.m16n8k16.row.col.f32.bf16.bf16.f32 "
                 "{%0,%1,%2,%3},{%4,%5,%6,%7},{%8,%9},{%0,%1,%2,%3};"
                 : "+f"(c[0]), "+f"(c[1]), "+f"(c[2]), "+f"(c[3])
                 : "r"(a0), "r"(a1), "r"(a2), "r"(a3), "r"(b0), "r"(b1));
}
__device__ __forceinline__ void mmaA(float* c, const uint4& a, u32 b0, u32 b1) {
    mma16816(c, a.x, a.y, a.z, a.w, b0, b1);
}
__device__ __forceinline__ uint4 ldm4(u32 addr) {
    uint4 r;
    asm volatile("ldmatrix.sync.aligned.m8n8.x4.shared.b16 {%0,%1,%2,%3}, [%4];"
                 : "=r"(r.x), "=r"(r.y), "=r"(r.z), "=r"(r.w) : "r"(addr));
    return r;
}

// ---------------------------------------------------------------------------
// wprep: W [E][H] f32 -> W^T [H][E] hi/lo bf16, smem-tiled transpose.
// ---------------------------------------------------------------------------
__global__ __launch_bounds__(256) void wprep_kernel(
    const float* __restrict__ wq, const float* __restrict__ wk,
    const float* __restrict__ wv)
{
    __shared__ float Ws[64][132];
    const int m = blockIdx.x >> 4, chunk = blockIdx.x & 15;
    const float* __restrict__ src = (m == 0) ? wq : (m == 1) ? wk : wv;
    const int e0 = chunk * 64;
    const int tid = threadIdx.x;

#pragma unroll
    for (int i = 0; i < 8; i++) {
        int id = tid + i * 256;
        int e = id >> 5, hc = (id & 31) * 4;
        *(float4*)&Ws[e][hc] = *(const float4*)&src[(size_t)(e0 + e) * HH + hc];
    }
    __syncthreads();

    const int h = tid >> 1, eh = (tid & 1) * 32;
    union { __nv_bfloat16 v[32]; uint4 u[4]; } Hh, Ll;
#pragma unroll
    for (int j = 0; j < 32; j++) {
        float f = Ws[eh + j][h];
        __nv_bfloat16 hi = __float2bfloat16_rn(f);
        Hh.v[j] = hi;
        Ll.v[j] = __float2bfloat16_rn(f - __bfloat162float(hi));
    }
    size_t ob = (size_t)h * EE + e0 + eh;
#pragma unroll
    for (int j = 0; j < 4; j++) {
        *(uint4*)&g_wth[m][ob + j*8] = Hh.u[j];
        *(uint4*)&g_wtl[m][ob + j*8] = Ll.u[j];
    }
}

// ---------------------------------------------------------------------------
// proj: unchanged (256 thr, warp tile 64x32, merged q+k / v CTAs, fused X
// f32->bf16 split, cp.async 2-stage). Tiles [128][72] bf16 (144B pitch).
// ---------------------------------------------------------------------------
#define PJ_T 18432            // 128*72*2
#define PROJ_SMEM (2 * 5 * PJ_T)   // 184320

__device__ __forceinline__ void chunk_load(u32 dst, const __nv_bfloat16* src) {
    int tid = threadIdx.x;
#pragma unroll
    for (int i = 0; i < 4; i++) {
        int id = tid + i * 256;
        int r = id >> 3, q = id & 7;
        cpa16(dst + r * 144 + q * 16, (const char*)src + (size_t)r * 2048 + q * 16);
    }
}
__device__ __forceinline__ void ldg_x(float4* xr, const float* __restrict__ x,
                                      int row0, int e0, int r, int half) {
    const float4* s = (const float4*)(x + (size_t)(row0 + r) * EE + e0 + half * 32);
#pragma unroll
    for (int i = 0; i < 8; i++) xr[i] = s[i];
}
__device__ __forceinline__ void conv_store_hi(char* xh_tile, const float4* xr,
                                              int r, int half) {
    const float* f = (const float*)xr;
    u32 h[16];
#pragma unroll
    for (int j = 0; j < 16; j++) h[j] = packbf(f[2*j], f[2*j+1]);
    char* p = xh_tile + r * 144 + half * 64;
#pragma unroll
    for (int q = 0; q < 4; q++)
        *(uint4*)(p + q*16) = make_uint4(h[4*q], h[4*q+1], h[4*q+2], h[4*q+3]);
}
__device__ __forceinline__ void conv_store_hilo(char* xh_tile, char* xl_tile,
                                                const float4* xr, int r, int half) {
    const float* f = (const float*)xr;
    u32 h[16], l[16];
#pragma unroll
    for (int j = 0; j < 16; j++) {
        h[j] = packbf(f[2*j], f[2*j+1]);
        l[j] = packlo(f[2*j], f[2*j+1], h[j]);
    }
    char* p = xh_tile + r * 144 + half * 64;
    char* q2 = xl_tile + r * 144 + half * 64;
#pragma unroll
    for (int q = 0; q < 4; q++) {
        *(uint4*)(p + q*16)  = make_uint4(h[4*q], h[4*q+1], h[4*q+2], h[4*q+3]);
        *(uint4*)(q2 + q*16) = make_uint4(l[4*q], l[4*q+1], l[4*q+2], l[4*q+3]);
    }
}

__global__ __launch_bounds__(256) void proj_kernel(const float* __restrict__ x) {
    extern __shared__ char sm[];
    const u32 sb = smem_u32(sm);
    const int tid = threadIdx.x, w = tid >> 5, lane = tid & 31;
    const int wy = w >> 2, wx = w & 3;
    const int g = lane >> 2, tg = lane & 3;
    const int row0 = blockIdx.x * 128;
    const bool isqk = (blockIdx.y == 0);
    const int xr_r = tid >> 1, xr_half = tid & 1;

    const u32 aoff = (u32)((wy*64 + (lane & 15)) * 144 + ((lane >> 4) & 1) * 16);
    const u32 boff = (u32)((wx*32 + (lane & 7) + ((lane >> 4) & 1) * 8) * 144
                           + ((lane >> 3) & 1) * 16);

    float c0[16][4], c1[16][4];
#pragma unroll
    for (int n = 0; n < 16; n++)
#pragma unroll
        for (int j = 0; j < 4; j++) { c0[n][j] = 0.0f; c1[n][j] = 0.0f; }

    const u32 STG = (isqk ? 5u : 4u) * PJ_T;

    float4 xr[8];
    ldg_x(xr, x, row0, 0, xr_r, xr_half);
    if (isqk) {
        conv_store_hi(sm, xr, xr_r, xr_half);
        chunk_load(sb + PJ_T,   g_wth[0]);
        chunk_load(sb + 2*PJ_T, g_wtl[0]);
        chunk_load(sb + 3*PJ_T, g_wth[1]);
        chunk_load(sb + 4*PJ_T, g_wtl[1]);
    } else {
        conv_store_hilo(sm, sm + PJ_T, xr, xr_r, xr_half);
        chunk_load(sb + 2*PJ_T, g_wth[2]);
        chunk_load(sb + 3*PJ_T, g_wtl[2]);
    }
    CP_COMMIT();
    ldg_x(xr, x, row0, 64, xr_r, xr_half);

    for (int ch = 0; ch < 16; ch++) {
        int cur = ch & 1;
        if (ch < 15) {
            char* np = sm + (cur ^ 1) * STG;
            u32 nb = sb + (cur ^ 1) * STG;
            int o = (ch + 1) * 64;
            if (isqk) {
                chunk_load(nb + PJ_T,   g_wth[0] + o);
                chunk_load(nb + 2*PJ_T, g_wtl[0] + o);
                chunk_load(nb + 3*PJ_T, g_wth[1] + o);
                chunk_load(nb + 4*PJ_T, g_wtl[1] + o);
            } else {
                chunk_load(nb + 2*PJ_T, g_wth[2] + o);
                chunk_load(nb + 3*PJ_T, g_wtl[2] + o);
            }
            CP_COMMIT();
            if (isqk) conv_store_hi(np, xr, xr_r, xr_half);
            else      conv_store_hilo(np, np + PJ_T, xr, xr_r, xr_half);
            if (ch < 14) ldg_x(xr, x, row0, (ch + 2) * 64, xr_r, xr_half);
            CP_WAIT(1);
        } else {
            CP_WAIT(0);
        }
        __syncthreads();
        const u32 base = sb + cur * STG;

        if (isqk) {
#pragma unroll
            for (int kt = 0; kt < 4; kt++) {
                uint4 A[4];
#pragma unroll
                for (int mf = 0; mf < 4; mf++)
                    A[mf] = ldm4(base + aoff + mf*2304 + kt*32);
                {
                    uint4 B0 = ldm4(base + PJ_T + boff + kt*32);
                    uint4 B1 = ldm4(base + PJ_T + boff + 2304 + kt*32);
#pragma unroll
                    for (int mf = 0; mf < 4; mf++) {
                        mmaA(c0[mf*4+0], A[mf], B0.x, B0.y);
                        mmaA(c0[mf*4+1], A[mf], B0.z, B0.w);
                        mmaA(c0[mf*4+2], A[mf], B1.x, B1.y);
                        mmaA(c0[mf*4+3], A[mf], B1.z, B1.w);
                    }
                }
                {
                    uint4 B0 = ldm4(base + 3*PJ_T + boff + kt*32);
                    uint4 B1 = ldm4(base + 3*PJ_T + boff + 2304 + kt*32);
#pragma unroll
                    for (int mf = 0; mf < 4; mf++) {
                        mmaA(c1[mf*4+0], A[mf], B0.x, B0.y);
                        mmaA(c1[mf*4+1], A[mf], B0.z, B0.w);
                        mmaA(c1[mf*4+2], A[mf], B1.x, B1.y);
                        mmaA(c1[mf*4+3], A[mf], B1.z, B1.w);
                    }
                }
                {
                    uint4 B0 = ldm4(base + 2*PJ_T + boff + kt*32);
                    uint4 B1 = ldm4(base + 2*PJ_T + boff + 2304 + kt*32);
#pragma unroll
                    for (int mf = 0; mf < 4; mf++) {
                        mmaA(c0[mf*4+0], A[mf], B0.x, B0.y);
                        mmaA(c0[mf*4+1], A[mf], B0.z, B0.w);
                        mmaA(c0[mf*4+2], A[mf], B1.x, B1.y);
                        mmaA(c0[mf*4+3], A[mf], B1.z, B1.w);
                    }
                }
                {
                    uint4 B0 = ldm4(base + 4*PJ_T + boff + kt*32);
                    uint4 B1 = ldm4(base + 4*PJ_T + boff + 2304 + kt*32);
#pragma unroll
                    for (int mf = 0; mf < 4; mf++) {
                        mmaA(c1[mf*4+0], A[mf], B0.x, B0.y);
                        mmaA(c1[mf*4+1], A[mf], B0.z, B0.w);
                        mmaA(c1[mf*4+2], A[mf], B1.x, B1.y);
                        mmaA(c1[mf*4+3], A[mf], B1.z, B1.w);
                    }
                }
            }
        } else {
#pragma unroll
            for (int kt = 0; kt < 4; kt++) {
                uint4 A[4], AL[4];
#pragma unroll
                for (int mf = 0; mf < 4; mf++) {
                    A[mf]  = ldm4(base + aoff + mf*2304 + kt*32);
                    AL[mf] = ldm4(base + PJ_T + aoff + mf*2304 + kt*32);
                }
                uint4 Bh0 = ldm4(base + 2*PJ_T + boff + kt*32);
                uint4 Bh1 = ldm4(base + 2*PJ_T + boff + 2304 + kt*32);
                uint4 Bl0 = ldm4(base + 3*PJ_T + boff + kt*32);
                uint4 Bl1 = ldm4(base + 3*PJ_T + boff + 2304 + kt*32);
#pragma unroll
                for (int mf = 0; mf < 4; mf++) {
                    mmaA(c0[mf*4+0], A[mf], Bh0.x, Bh0.y);
                    mmaA(c0[mf*4+1], A[mf], Bh0.z, Bh0.w);
                    mmaA(c0[mf*4+2], A[mf], Bh1.x, Bh1.y);
                    mmaA(c0[mf*4+3], A[mf], Bh1.z, Bh1.w);
                }
#pragma unroll
                for (int mf = 0; mf < 4; mf++) {
                    mmaA(c0[mf*4+0], A[mf], Bl0.x, Bl0.y);
                    mmaA(c0[mf*4+1], A[mf], Bl0.z, Bl0.w);
                    mmaA(c0[mf*4+2], A[mf], Bl1.x, Bl1.y);
                    mmaA(c0[mf*4+3], A[mf], Bl1.z, Bl1.w);
                }
#pragma unroll
                for (int mf = 0; mf < 4; mf++) {
                    mmaA(c0[mf*4+0], AL[mf], Bh0.x, Bh0.y);
                    mmaA(c0[mf*4+1], AL[mf], Bh0.z, Bh0.w);
                    mmaA(c0[mf*4+2], AL[mf], Bh1.x, Bh1.y);
                    mmaA(c0[mf*4+3], AL[mf], Bh1.z, Bh1.w);
                }
            }
        }
        __syncthreads();
    }

    if (isqk) {
#pragma unroll
        for (int mf = 0; mf < 4; mf++) {
            size_t rA = (size_t)(row0 + wy*64 + mf*16 + g) * HH;
            size_t rB = rA + 8 * HH;
#pragma unroll
            for (int f = 0; f < 4; f++) {
                int col = wx*32 + (f >> 1)*16 + (f & 1)*8 + tg*2;
                const float* cq = c0[mf*4 + f];
                const float* ck = c1[mf*4 + f];
                u32 qh0 = packbf(cq[0], cq[1]);
                u32 qh1 = packbf(cq[2], cq[3]);
                *(u32*)&g_qh[rA + col] = qh0;
                *(u32*)&g_qh[rB + col] = qh1;
                *(u32*)&g_ql[rA + col] = packlo(cq[0], cq[1], qh0);
                *(u32*)&g_ql[rB + col] = packlo(cq[2], cq[3], qh1);
                *(u32*)&g_kh[rA + col] = packbf(ck[0], ck[1]);
                *(u32*)&g_kh[rB + col] = packbf(ck[2], ck[3]);
            }
        }
    } else {
        float* Cs = (float*)sm;   // [128][132]
#pragma unroll
        for (int mf = 0; mf < 4; mf++) {
            int r = wy*64 + mf*16 + g;
#pragma unroll
            for (int f = 0; f < 4; f++) {
                int col = wx*32 + (f >> 1)*16 + (f & 1)*8 + tg*2;
                const float* cv = c0[mf*4 + f];
                Cs[r * 132 + col]           = cv[0];
                Cs[r * 132 + col + 1]       = cv[1];
                Cs[(r + 8) * 132 + col]     = cv[2];
                Cs[(r + 8) * 132 + col + 1] = cv[3];
            }
        }
        __syncthreads();
        int h = tid >> 1, half = tid & 1;
        int b = row0 >> 11, s0 = row0 & 2047;
        union { __nv_bfloat16 v[64]; uint4 u[8]; } Hh, Ll;
#pragma unroll
        for (int j = 0; j < 64; j++) {
            float f = Cs[(half*64 + j) * 132 + h];
            __nv_bfloat16 hi = __float2bfloat16_rn(f);
            Hh.v[j] = hi;
            Ll.v[j] = __float2bfloat16_rn(f - __bfloat162float(hi));
        }
        size_t ob = ((size_t)(b*HH + h)) * SS + s0 + half*64;
#pragma unroll
        for (int j = 0; j < 8; j++) {
            *(uint4*)&g_vth[ob + j*8] = Hh.u[j];
            *(uint4*)&g_vtl[ob + j*8] = Ll.u[j];
        }
    }
}

// ---------------------------------------------------------------------------
// attn v3: CTA = 128 Q rows x one batch, 256 threads (8 warps, warp = 16 rows),
// key tiles of 128 split into two 64-key COMPUTE halves inside the CTA:
// QK(h0) -> softmax+PV(h0) -> QK(h1) -> softmax+PV(h1). Halving the live
// accumulator block (c[8][4], kb[4]) cuts peak register pressure (~255 -> ~200,
// removing spills). PV pass order: Ph*Vh, Pl*Vh (vb reg-cached), Ph*Vl (inline).
// Dropout bits built in-loop per half. smem: Qh,Ql,Kh,Vth,Vtl [128][136].
// ---------------------------------------------------------------------------
#define AT_T 34816            // 128*136*2
#define ATT_SMEM (5 * AT_T)

__device__ __forceinline__ void tile_load(u32 dst, const __nv_bfloat16* src,
                                          int stride_elems) {
    int tid = threadIdx.x;
#pragma unroll
    for (int i = 0; i < 8; i++) {
        int id = tid + i * 256;
        int r = id >> 4, q = id & 15;
        cpa16(dst + r * 272 + q * 16,
              (const char*)src + (size_t)r * stride_elems * 2 + q * 16);
    }
}

// QK over one 64-key half: c[8][4] accums, dropout keep-bits for the half.
__device__ __forceinline__ void qk_half(
    float (*c)[4], u32 Qh, u32 Ql, u32 Kh, u32 aoff, u32 boffK,
    const float* __restrict__ duA, const float* __restrict__ duB,
    u32& wa, u32& wb, int tg)
{
#pragma unroll
    for (int n = 0; n < 8; n++)
#pragma unroll
        for (int j = 0; j < 4; j++) c[n][j] = 0.0f;
    wa = 0; wb = 0;
#pragma unroll
    for (int kt = 0; kt < 8; kt++) {
        {
            float2 a0 = *(const float2*)(duA + kt*8 + tg*2);
            float2 b0 = *(const float2*)(duB + kt*8 + tg*2);
            wa |= ((a0.x >= 0.1f) ? 1u : 0u) << (2*kt)
                | ((a0.y >= 0.1f) ? 1u : 0u) << (2*kt+1);
            wb |= ((b0.x >= 0.1f) ? 1u : 0u) << (2*kt)
                | ((b0.y >= 0.1f) ? 1u : 0u) << (2*kt+1);
        }
        uint4 AH = ldm4(Qh + aoff + kt*32);
        uint4 AL = ldm4(Ql + aoff + kt*32);
        uint4 kb[4];
#pragma unroll
        for (int np = 0; np < 4; np++) kb[np] = ldm4(Kh + boffK + np*4352 + kt*32);
        // pass 1: Qh * Kh
#pragma unroll
        for (int np = 0; np < 4; np++) {
            mmaA(c[2*np], AH, kb[np].x, kb[np].y);
            mmaA(c[2*np+1], AH, kb[np].z, kb[np].w);
        }
        // pass 2: Ql * Kh (reg-cached frags)
#pragma unroll
        for (int np = 0; np < 4; np++) {
            mmaA(c[2*np], AL, kb[np].x, kb[np].y);
            mmaA(c[2*np+1], AL, kb[np].z, kb[np].w);
        }
    }
}

// softmax + dropout(numerator only) + PV over one 64-key half.
__device__ __forceinline__ void spv_half(
    float (*o)[4], float (*c)[4], u32 wa, u32 wb,
    u32 Vh, u32 Vl, u32 boffV, float& lsumA, float& lsumB)
{
    const float SC = 0.03125f;        // 1024^-0.5
    const float INVK = 1.0f / 0.9f;
#pragma unroll
    for (int kt = 0; kt < 4; kt++) {
        u32 ph[4], pl[4];
#pragma unroll
        for (int half = 0; half < 2; half++) {
            int n = 2*kt + half;
            int sh = 2*n;
            float p0 = __expf(c[n][0] * SC), p1 = __expf(c[n][1] * SC);
            float p2 = __expf(c[n][2] * SC), p3 = __expf(c[n][3] * SC);
            lsumA += p0 + p1;
            lsumB += p2 + p3;
            p0 *= ((wa >> sh) & 1)     ? INVK : 0.0f;
            p1 *= ((wa >> (sh+1)) & 1) ? INVK : 0.0f;
            p2 *= ((wb >> sh) & 1)     ? INVK : 0.0f;
            p3 *= ((wb >> (sh+1)) & 1) ? INVK : 0.0f;
            ph[2*half]     = packbf(p0, p1);
            pl[2*half]     = packlo(p0, p1, ph[2*half]);
            ph[2*half + 1] = packbf(p2, p3);
            pl[2*half + 1] = packlo(p2, p3, ph[2*half + 1]);
        }
        uint4 vb[8];
#pragma unroll
        for (int np = 0; np < 8; np++) vb[np] = ldm4(Vh + boffV + np*4352 + kt*32);
        // pass 1: Ph * Vh (cached frags)
#pragma unroll
        for (int np = 0; np < 8; np++) {
            mma16816(o[2*np], ph[0], ph[1], ph[2], ph[3], vb[np].x, vb[np].y);
            mma16816(o[2*np+1], ph[0], ph[1], ph[2], ph[3], vb[np].z, vb[np].w);
        }
        // pass 2: Pl * Vh (cached frags, adjacent use -> short vb live range)
#pragma unroll
        for (int np = 0; np < 8; np++) {
            mma16816(o[2*np], pl[0], pl[1], pl[2], pl[3], vb[np].x, vb[np].y);
            mma16816(o[2*np+1], pl[0], pl[1], pl[2], pl[3], vb[np].z, vb[np].w);
        }
        // pass 3: Ph * Vl (inline loads)
#pragma unroll
        for (int np = 0; np < 8; np++) {
            uint4 B = ldm4(Vl + boffV + np*4352 + kt*32);
            mma16816(o[2*np], ph[0], ph[1], ph[2], ph[3], B.x, B.y);
            mma16816(o[2*np+1], ph[0], ph[1], ph[2], ph[3], B.z, B.w);
        }
    }
}

__global__ __launch_bounds__(256) void attn_kernel(
    const float* __restrict__ du_g, float* __restrict__ out)
{
    extern __shared__ char sm[];
    const u32 sb = smem_u32(sm);
    const int tid = threadIdx.x, w = tid >> 5, lane = tid & 31;
    const int g = lane >> 2, tg = lane & 3;
    const int b = blockIdx.y;
    const int q0 = blockIdx.x * 128;

    const u32 Qh = sb, Ql = sb + AT_T, Kh = sb + 2*AT_T;
    const u32 Vh = sb + 3*AT_T, Vl = sb + 4*AT_T;

    const u32 aoff = (u32)((w*16 + (lane & 15)) * 272 + ((lane >> 4) & 1) * 16);
    const u32 boff = (u32)(((lane & 7) + ((lane >> 4) & 1) * 8) * 272 + ((lane >> 3) & 1) * 16);

    const size_t qoff = (size_t)(b*SS + q0) * HH;
    tile_load(Qh, g_qh + qoff, HH);
    tile_load(Ql, g_ql + qoff, HH);
    tile_load(Kh, g_kh + (size_t)(b*SS) * HH, HH);
    CP_COMMIT();

    float o[16][4];
#pragma unroll
    for (int n = 0; n < 16; n++)
#pragma unroll
        for (int j = 0; j < 4; j++) o[n][j] = 0.0f;
    float lsumA = 0.0f, lsumB = 0.0f;

    const float* duA = du_g + ((size_t)(b*SS) + q0 + w*16 + g) * SS;
    const float* duB = duA + 8 * SS;

    CP_WAIT(0);
    __syncthreads();

    for (int t = 0; t < 16; t++) {
        const int k0 = t * 128;
        // V(t) load overlaps QK(t, half0)
        tile_load(Vh, g_vth + (size_t)(b*HH) * SS + k0, SS);
        tile_load(Vl, g_vtl + (size_t)(b*HH) * SS + k0, SS);
        CP_COMMIT();

        float c[8][4];
        u32 wa, wb;

        // ---- half 0: keys k0 .. k0+63 ----
        qk_half(c, Qh, Ql, Kh, aoff, boff, duA + k0, duB + k0, wa, wb, tg);
        CP_WAIT(0);          // V(t) ready
        __syncthreads();     // cp.async visibility across threads
        spv_half(o, c, wa, wb, Vh, Vl, boff, lsumA, lsumB);

        // ---- half 1: keys k0+64 .. k0+127 ----
        qk_half(c, Qh, Ql, Kh, aoff, boff + 64*272,
                duA + k0 + 64, duB + k0 + 64, wa, wb, tg);
        __syncthreads();     // all warps done reading Kh(t)
        if (t < 15) {
            tile_load(Kh, g_kh + (size_t)(b*SS + k0 + 128) * HH, HH);
            CP_COMMIT();
        }
        spv_half(o, c, wa, wb, Vh, Vl, boff + 128, lsumA, lsumB);

        if (t < 15) CP_WAIT(0);   // K(t+1) ready
        __syncthreads();          // V buffer reuse safety
    }

    // per-row softmax denominators: reduce over quad lanes
#pragma unroll
    for (int off = 1; off <= 2; off <<= 1) {
        lsumA += __shfl_xor_sync(0xffffffffu, lsumA, off);
        lsumB += __shfl_xor_sync(0xffffffffu, lsumB, off);
    }
    const float invA = 1.0f / lsumA, invB = 1.0f / lsumB;

    float* oA = out + ((size_t)(b*SS) + q0 + w*16 + g) * HH;
    float* oB = oA + 8 * HH;
#pragma unroll
    for (int n = 0; n < 16; n++) {
        int col = n*8 + tg*2;
        *(float2*)(oA + col) = make_float2(o[n][0] * invA, o[n][1] * invA);
        *(float2*)(oB + col) = make_float2(o[n][2] * invB, o[n][3] * invB);
    }
}

extern "C" void kernel_launch(void* const* d_in, const int* in_sizes, int n_in,
                              void* d_out, int out_size)
{
    const float* x  = (const float*)d_in[0];
    const float* wq = (const float*)d_in[1];
    const float* wk = (const float*)d_in[2];
    const float* wv = (const float*)d_in[3];
    const float* du = (const float*)d_in[4];
    float* out = (float*)d_out;

    cudaFuncSetAttribute(proj_kernel, cudaFuncAttributeMaxDynamicSharedMemorySize, PROJ_SMEM);
    cudaFuncSetAttribute(attn_kernel, cudaFuncAttributeMaxDynamicSharedMemorySize, ATT_SMEM);

    wprep_kernel<<<48, 256>>>(wq, wk, wv);
    dim3 g1(BB*SS / 128, 2);
    proj_kernel<<<g1, 256, PROJ_SMEM>>>(x);
    dim3 g2(SS / 128, BB);
    attn_kernel<<<g2, 256, ATT_SMEM>>>(du, out);
}

// round 16
// speedup vs baseline: 1.0135x; 1.0135x over previous
#include <cuda_runtime.h>
#include <cuda_bf16.h>

#define BB 8
#define SS 2048
#define EE 1024
#define HH 128

typedef unsigned int u32;

// ---------------- device scratch ----------------
__device__ __nv_bfloat16 g_wth[3][HH*EE], g_wtl[3][HH*EE];   // W^T split [h][e]
__device__ __nv_bfloat16 g_qh[BB*SS*HH], g_ql[BB*SS*HH];     // Q [s][h]
__device__ __nv_bfloat16 g_kh[BB*SS*HH];                     // K hi [s][h]
__device__ __nv_bfloat16 g_vth[BB*HH*SS], g_vtl[BB*HH*SS];   // V^T [b][h][s]

// ---------------- helpers ----------------
__device__ __forceinline__ u32 smem_u32(const void* p) {
    u32 a;
    asm("{ .reg .u64 t; cvta.to.shared.u64 t, %1; cvt.u32.u64 %0, t; }" : "=r"(a) : "l"(p));
    return a;
}
__device__ __forceinline__ void cpa16(u32 dst, const void* src) {
    asm volatile("cp.async.cg.shared.global [%0], [%1], 16;" :: "r"(dst), "l"(src));
}
#define CP_COMMIT() asm volatile("cp.async.commit_group;" ::: "memory")
#define CP_WAIT(n)  asm volatile("cp.async.wait_group %0;" :: "n"(n) : "memory")

__device__ __forceinline__ u32 packbf(float lo, float hi) {
    u32 r;
    asm("cvt.rn.bf16x2.f32 %0, %1, %2;" : "=r"(r) : "f"(hi), "f"(lo));
    return r;
}
__device__ __forceinline__ u32 packlo(float p0, float p1, u32 h) {
    float r0 = p0 - __uint_as_float(h << 16);
    float r1 = p1 - __uint_as_float(h & 0xffff0000u);
    return packbf(r0, r1);
}
__device__ __forceinline__ void mma16816(float* c, u32 a0, u32 a1, u32 a2, u32 a3,
                                         u32 b0, u32 b1) {
    asm volatile("mma.sync.aligned.m16n8k16.row.col.f32.bf16.bf16.f32 "
                 "{%0,%1,%2,%3},{%4,%5,%6,%7},{%8,%9},{%0,%1,%2,%3};"
                 : "+f"(c[0]), "+f"(c[1]), "+f"(c[2]), "+f"(c[3])
                 : "r"(a0), "r"(a1), "r"(a2), "r"(a3), "r"(b0), "r"(b1));
}
__device__ __forceinline__ void mmaA(float* c, const uint4& a, u32 b0, u32 b1) {
    mma16816(c, a.x, a.y, a.z, a.w, b0, b1);
}
__device__ __forceinline__ uint4 ldm4(u32 addr) {
    uint4 r;
    asm volatile("ldmatrix.sync.aligned.m8n8.x4.shared.b16 {%0,%1,%2,%3}, [%4];"
                 : "=r"(r.x), "=r"(r.y), "=r"(r.z), "=r"(r.w) : "r"(addr));
    return r;
}

// ---------------------------------------------------------------------------
// wprep: W [E][H] f32 -> W^T [H][E] hi/lo bf16, smem-tiled transpose.
// ---------------------------------------------------------------------------
__global__ __launch_bounds__(256) void wprep_kernel(
    const float* __restrict__ wq, const float* __restrict__ wk,
    const float* __restrict__ wv)
{
    __shared__ float Ws[64][132];
    const int m = blockIdx.x >> 4, chunk = blockIdx.x & 15;
    const float* __restrict__ src = (m == 0) ? wq : (m == 1) ? wk : wv;
    const int e0 = chunk * 64;
    const int tid = threadIdx.x;

#pragma unroll
    for (int i = 0; i < 8; i++) {
        int id = tid + i * 256;
        int e = id >> 5, hc = (id & 31) * 4;
        *(float4*)&Ws[e][hc] = *(const float4*)&src[(size_t)(e0 + e) * HH + hc];
    }
    __syncthreads();

    const int h = tid >> 1, eh = (tid & 1) * 32;
    union { __nv_bfloat16 v[32]; uint4 u[4]; } Hh, Ll;
#pragma unroll
    for (int j = 0; j < 32; j++) {
        float f = Ws[eh + j][h];
        __nv_bfloat16 hi = __float2bfloat16_rn(f);
        Hh.v[j] = hi;
        Ll.v[j] = __float2bfloat16_rn(f - __bfloat162float(hi));
    }
    size_t ob = (size_t)h * EE + e0 + eh;
#pragma unroll
    for (int j = 0; j < 4; j++) {
        *(uint4*)&g_wth[m][ob + j*8] = Hh.u[j];
        *(uint4*)&g_wtl[m][ob + j*8] = Ll.u[j];
    }
}

// ---------------------------------------------------------------------------
// proj: unchanged (256 thr, warp tile 64x32, merged q+k / v CTAs, fused X
// f32->bf16 split, cp.async 2-stage). Tiles [128][72] bf16 (144B pitch).
// ---------------------------------------------------------------------------
#define PJ_T 18432            // 128*72*2
#define PROJ_SMEM (2 * 5 * PJ_T)   // 184320

__device__ __forceinline__ void chunk_load(u32 dst, const __nv_bfloat16* src) {
    int tid = threadIdx.x;
#pragma unroll
    for (int i = 0; i < 4; i++) {
        int id = tid + i * 256;
        int r = id >> 3, q = id & 7;
        cpa16(dst + r * 144 + q * 16, (const char*)src + (size_t)r * 2048 + q * 16);
    }
}
__device__ __forceinline__ void ldg_x(float4* xr, const float* __restrict__ x,
                                      int row0, int e0, int r, int half) {
    const float4* s = (const float4*)(x + (size_t)(row0 + r) * EE + e0 + half * 32);
#pragma unroll
    for (int i = 0; i < 8; i++) xr[i] = s[i];
}
__device__ __forceinline__ void conv_store_hi(char* xh_tile, const float4* xr,
                                              int r, int half) {
    const float* f = (const float*)xr;
    u32 h[16];
#pragma unroll
    for (int j = 0; j < 16; j++) h[j] = packbf(f[2*j], f[2*j+1]);
    char* p = xh_tile + r * 144 + half * 64;
#pragma unroll
    for (int q = 0; q < 4; q++)
        *(uint4*)(p + q*16) = make_uint4(h[4*q], h[4*q+1], h[4*q+2], h[4*q+3]);
}
__device__ __forceinline__ void conv_store_hilo(char* xh_tile, char* xl_tile,
                                                const float4* xr, int r, int half) {
    const float* f = (const float*)xr;
    u32 h[16], l[16];
#pragma unroll
    for (int j = 0; j < 16; j++) {
        h[j] = packbf(f[2*j], f[2*j+1]);
        l[j] = packlo(f[2*j], f[2*j+1], h[j]);
    }
    char* p = xh_tile + r * 144 + half * 64;
    char* q2 = xl_tile + r * 144 + half * 64;
#pragma unroll
    for (int q = 0; q < 4; q++) {
        *(uint4*)(p + q*16)  = make_uint4(h[4*q], h[4*q+1], h[4*q+2], h[4*q+3]);
        *(uint4*)(q2 + q*16) = make_uint4(l[4*q], l[4*q+1], l[4*q+2], l[4*q+3]);
    }
}

__global__ __launch_bounds__(256) void proj_kernel(const float* __restrict__ x) {
    extern __shared__ char sm[];
    const u32 sb = smem_u32(sm);
    const int tid = threadIdx.x, w = tid >> 5, lane = tid & 31;
    const int wy = w >> 2, wx = w & 3;
    const int g = lane >> 2, tg = lane & 3;
    const int row0 = blockIdx.x * 128;
    const bool isqk = (blockIdx.y == 0);
    const int xr_r = tid >> 1, xr_half = tid & 1;

    const u32 aoff = (u32)((wy*64 + (lane & 15)) * 144 + ((lane >> 4) & 1) * 16);
    const u32 boff = (u32)((wx*32 + (lane & 7) + ((lane >> 4) & 1) * 8) * 144
                           + ((lane >> 3) & 1) * 16);

    float c0[16][4], c1[16][4];
#pragma unroll
    for (int n = 0; n < 16; n++)
#pragma unroll
        for (int j = 0; j < 4; j++) { c0[n][j] = 0.0f; c1[n][j] = 0.0f; }

    const u32 STG = (isqk ? 5u : 4u) * PJ_T;

    float4 xr[8];
    ldg_x(xr, x, row0, 0, xr_r, xr_half);
    if (isqk) {
        conv_store_hi(sm, xr, xr_r, xr_half);
        chunk_load(sb + PJ_T,   g_wth[0]);
        chunk_load(sb + 2*PJ_T, g_wtl[0]);
        chunk_load(sb + 3*PJ_T, g_wth[1]);
        chunk_load(sb + 4*PJ_T, g_wtl[1]);
    } else {
        conv_store_hilo(sm, sm + PJ_T, xr, xr_r, xr_half);
        chunk_load(sb + 2*PJ_T, g_wth[2]);
        chunk_load(sb + 3*PJ_T, g_wtl[2]);
    }
    CP_COMMIT();
    ldg_x(xr, x, row0, 64, xr_r, xr_half);

    for (int ch = 0; ch < 16; ch++) {
        int cur = ch & 1;
        if (ch < 15) {
            char* np = sm + (cur ^ 1) * STG;
            u32 nb = sb + (cur ^ 1) * STG;
            int o = (ch + 1) * 64;
            if (isqk) {
                chunk_load(nb + PJ_T,   g_wth[0] + o);
                chunk_load(nb + 2*PJ_T, g_wtl[0] + o);
                chunk_load(nb + 3*PJ_T, g_wth[1] + o);
                chunk_load(nb + 4*PJ_T, g_wtl[1] + o);
            } else {
                chunk_load(nb + 2*PJ_T, g_wth[2] + o);
                chunk_load(nb + 3*PJ_T, g_wtl[2] + o);
            }
            CP_COMMIT();
            if (isqk) conv_store_hi(np, xr, xr_r, xr_half);
            else      conv_store_hilo(np, np + PJ_T, xr, xr_r, xr_half);
            if (ch < 14) ldg_x(xr, x, row0, (ch + 2) * 64, xr_r, xr_half);
            CP_WAIT(1);
        } else {
            CP_WAIT(0);
        }
        __syncthreads();
        const u32 base = sb + cur * STG;

        if (isqk) {
#pragma unroll
            for (int kt = 0; kt < 4; kt++) {
                uint4 A[4];
#pragma unroll
                for (int mf = 0; mf < 4; mf++)
                    A[mf] = ldm4(base + aoff + mf*2304 + kt*32);
                {
                    uint4 B0 = ldm4(base + PJ_T + boff + kt*32);
                    uint4 B1 = ldm4(base + PJ_T + boff + 2304 + kt*32);
#pragma unroll
                    for (int mf = 0; mf < 4; mf++) {
                        mmaA(c0[mf*4+0], A[mf], B0.x, B0.y);
                        mmaA(c0[mf*4+1], A[mf], B0.z, B0.w);
                        mmaA(c0[mf*4+2], A[mf], B1.x, B1.y);
                        mmaA(c0[mf*4+3], A[mf], B1.z, B1.w);
                    }
                }
                {
                    uint4 B0 = ldm4(base + 3*PJ_T + boff + kt*32);
                    uint4 B1 = ldm4(base + 3*PJ_T + boff + 2304 + kt*32);
#pragma unroll
                    for (int mf = 0; mf < 4; mf++) {
                        mmaA(c1[mf*4+0], A[mf], B0.x, B0.y);
                        mmaA(c1[mf*4+1], A[mf], B0.z, B0.w);
                        mmaA(c1[mf*4+2], A[mf], B1.x, B1.y);
                        mmaA(c1[mf*4+3], A[mf], B1.z, B1.w);
                    }
                }
                {
                    uint4 B0 = ldm4(base + 2*PJ_T + boff + kt*32);
                    uint4 B1 = ldm4(base + 2*PJ_T + boff + 2304 + kt*32);
#pragma unroll
                    for (int mf = 0; mf < 4; mf++) {
                        mmaA(c0[mf*4+0], A[mf], B0.x, B0.y);
                        mmaA(c0[mf*4+1], A[mf], B0.z, B0.w);
                        mmaA(c0[mf*4+2], A[mf], B1.x, B1.y);
                        mmaA(c0[mf*4+3], A[mf], B1.z, B1.w);
                    }
                }
                {
                    uint4 B0 = ldm4(base + 4*PJ_T + boff + kt*32);
                    uint4 B1 = ldm4(base + 4*PJ_T + boff + 2304 + kt*32);
#pragma unroll
                    for (int mf = 0; mf < 4; mf++) {
                        mmaA(c1[mf*4+0], A[mf], B0.x, B0.y);
                        mmaA(c1[mf*4+1], A[mf], B0.z, B0.w);
                        mmaA(c1[mf*4+2], A[mf], B1.x, B1.y);
                        mmaA(c1[mf*4+3], A[mf], B1.z, B1.w);
                    }
                }
            }
        } else {
#pragma unroll
            for (int kt = 0; kt < 4; kt++) {
                uint4 A[4], AL[4];
#pragma unroll
                for (int mf = 0; mf < 4; mf++) {
                    A[mf]  = ldm4(base + aoff + mf*2304 + kt*32);
                    AL[mf] = ldm4(base + PJ_T + aoff + mf*2304 + kt*32);
                }
                uint4 Bh0 = ldm4(base + 2*PJ_T + boff + kt*32);
                uint4 Bh1 = ldm4(base + 2*PJ_T + boff + 2304 + kt*32);
                uint4 Bl0 = ldm4(base + 3*PJ_T + boff + kt*32);
                uint4 Bl1 = ldm4(base + 3*PJ_T + boff + 2304 + kt*32);
#pragma unroll
                for (int mf = 0; mf < 4; mf++) {
                    mmaA(c0[mf*4+0], A[mf], Bh0.x, Bh0.y);
                    mmaA(c0[mf*4+1], A[mf], Bh0.z, Bh0.w);
                    mmaA(c0[mf*4+2], A[mf], Bh1.x, Bh1.y);
                    mmaA(c0[mf*4+3], A[mf], Bh1.z, Bh1.w);
                }
#pragma unroll
                for (int mf = 0; mf < 4; mf++) {
                    mmaA(c0[mf*4+0], A[mf], Bl0.x, Bl0.y);
                    mmaA(c0[mf*4+1], A[mf], Bl0.z, Bl0.w);
                    mmaA(c0[mf*4+2], A[mf], Bl1.x, Bl1.y);
                    mmaA(c0[mf*4+3], A[mf], Bl1.z, Bl1.w);
                }
#pragma unroll
                for (int mf = 0; mf < 4; mf++) {
                    mmaA(c0[mf*4+0], AL[mf], Bh0.x, Bh0.y);
                    mmaA(c0[mf*4+1], AL[mf], Bh0.z, Bh0.w);
                    mmaA(c0[mf*4+2], AL[mf], Bh1.x, Bh1.y);
                    mmaA(c0[mf*4+3], AL[mf], Bh1.z, Bh1.w);
                }
            }
        }
        __syncthreads();
    }

    if (isqk) {
#pragma unroll
        for (int mf = 0; mf < 4; mf++) {
            size_t rA = (size_t)(row0 + wy*64 + mf*16 + g) * HH;
            size_t rB = rA + 8 * HH;
#pragma unroll
            for (int f = 0; f < 4; f++) {
                int col = wx*32 + (f >> 1)*16 + (f & 1)*8 + tg*2;
                const float* cq = c0[mf*4 + f];
                const float* ck = c1[mf*4 + f];
                u32 qh0 = packbf(cq[0], cq[1]);
                u32 qh1 = packbf(cq[2], cq[3]);
                *(u32*)&g_qh[rA + col] = qh0;
                *(u32*)&g_qh[rB + col] = qh1;
                *(u32*)&g_ql[rA + col] = packlo(cq[0], cq[1], qh0);
                *(u32*)&g_ql[rB + col] = packlo(cq[2], cq[3], qh1);
                *(u32*)&g_kh[rA + col] = packbf(ck[0], ck[1]);
                *(u32*)&g_kh[rB + col] = packbf(ck[2], ck[3]);
            }
        }
    } else {
        float* Cs = (float*)sm;   // [128][132]
#pragma unroll
        for (int mf = 0; mf < 4; mf++) {
            int r = wy*64 + mf*16 + g;
#pragma unroll
            for (int f = 0; f < 4; f++) {
                int col = wx*32 + (f >> 1)*16 + (f & 1)*8 + tg*2;
                const float* cv = c0[mf*4 + f];
                Cs[r * 132 + col]           = cv[0];
                Cs[r * 132 + col + 1]       = cv[1];
                Cs[(r + 8) * 132 + col]     = cv[2];
                Cs[(r + 8) * 132 + col + 1] = cv[3];
            }
        }
        __syncthreads();
        int h = tid >> 1, half = tid & 1;
        int b = row0 >> 11, s0 = row0 & 2047;
        union { __nv_bfloat16 v[64]; uint4 u[8]; } Hh, Ll;
#pragma unroll
        for (int j = 0; j < 64; j++) {
            float f = Cs[(half*64 + j) * 132 + h];
            __nv_bfloat16 hi = __float2bfloat16_rn(f);
            Hh.v[j] = hi;
            Ll.v[j] = __float2bfloat16_rn(f - __bfloat162float(hi));
        }
        size_t ob = ((size_t)(b*HH + h)) * SS + s0 + half*64;
#pragma unroll
        for (int j = 0; j < 8; j++) {
            *(uint4*)&g_vth[ob + j*8] = Hh.u[j];
            *(uint4*)&g_vtl[ob + j*8] = Ll.u[j];
        }
    }
}

// ---------------------------------------------------------------------------
// attn (R11 structure): CTA = 128 Q rows x one batch, 256 threads, 8 warps,
// warp = 16 rows, monolithic 128-key tiles. QK 2-pass with K frags reg-cached.
// PV 3-pass ALL-INLINE B loads (no vb[8] cache -> 32 fewer live regs, no
// spills; +64 ldm4/tile is absorbed by L1 headroom). Dropout bits in-loop.
// smem: Qh,Ql,Kh,Vth,Vtl [128][136] (272B pitch).
// ---------------------------------------------------------------------------
#define AT_T 34816            // 128*136*2
#define ATT_SMEM (5 * AT_T)

__device__ __forceinline__ void tile_load(u32 dst, const __nv_bfloat16* src,
                                          int stride_elems) {
    int tid = threadIdx.x;
#pragma unroll
    for (int i = 0; i < 8; i++) {
        int id = tid + i * 256;
        int r = id >> 4, q = id & 15;
        cpa16(dst + r * 272 + q * 16,
              (const char*)src + (size_t)r * stride_elems * 2 + q * 16);
    }
}

__global__ __launch_bounds__(256) void attn_kernel(
    const float* __restrict__ du_g, float* __restrict__ out)
{
    extern __shared__ char sm[];
    const u32 sb = smem_u32(sm);
    const int tid = threadIdx.x, w = tid >> 5, lane = tid & 31;
    const int g = lane >> 2, tg = lane & 3;
    const int b = blockIdx.y;
    const int q0 = blockIdx.x * 128;

    const u32 Qh = sb, Ql = sb + AT_T, Kh = sb + 2*AT_T;
    const u32 Vh = sb + 3*AT_T, Vl = sb + 4*AT_T;

    const u32 aoff = (u32)((w*16 + (lane & 15)) * 272 + ((lane >> 4) & 1) * 16);
    const u32 boff = (u32)(((lane & 7) + ((lane >> 4) & 1) * 8) * 272 + ((lane >> 3) & 1) * 16);

    const size_t qoff = (size_t)(b*SS + q0) * HH;
    tile_load(Qh, g_qh + qoff, HH);
    tile_load(Ql, g_ql + qoff, HH);
    tile_load(Kh, g_kh + (size_t)(b*SS) * HH, HH);
    CP_COMMIT();

    float o[16][4];
#pragma unroll
    for (int n = 0; n < 16; n++)
#pragma unroll
        for (int j = 0; j < 4; j++) o[n][j] = 0.0f;
    float lsumA = 0.0f, lsumB = 0.0f;

    const float SC = 0.03125f;        // 1024^-0.5
    const float INVK = 1.0f / 0.9f;
    const float* duA = du_g + ((size_t)(b*SS) + q0 + w*16 + g) * SS;
    const float* duB = duA + 8 * SS;

    CP_WAIT(0);
    __syncthreads();

    for (int t = 0; t < 16; t++) {
        const int k0 = t * 128;
        // V(t) load overlaps QK(t)
        tile_load(Vh, g_vth + (size_t)(b*HH) * SS + k0, SS);
        tile_load(Vl, g_vtl + (size_t)(b*HH) * SS + k0, SS);
        CP_COMMIT();

        float c[16][4];
#pragma unroll
        for (int n = 0; n < 16; n++)
#pragma unroll
            for (int j = 0; j < 4; j++) c[n][j] = 0.0f;

        // dropout keep-bits: bit 2n -> key col n*8+tg*2
        u32 wa = 0, wb = 0;

#pragma unroll
        for (int kt = 0; kt < 8; kt++) {
            {
                float2 a0 = *(const float2*)(duA + k0 + kt*16 + tg*2);
                float2 a1 = *(const float2*)(duA + k0 + kt*16 + 8 + tg*2);
                float2 b0 = *(const float2*)(duB + k0 + kt*16 + tg*2);
                float2 b1 = *(const float2*)(duB + k0 + kt*16 + 8 + tg*2);
                wa |= ((a0.x >= 0.1f) ? 1u : 0u) << (4*kt)
                    | ((a0.y >= 0.1f) ? 1u : 0u) << (4*kt+1)
                    | ((a1.x >= 0.1f) ? 1u : 0u) << (4*kt+2)
                    | ((a1.y >= 0.1f) ? 1u : 0u) << (4*kt+3);
                wb |= ((b0.x >= 0.1f) ? 1u : 0u) << (4*kt)
                    | ((b0.y >= 0.1f) ? 1u : 0u) << (4*kt+1)
                    | ((b1.x >= 0.1f) ? 1u : 0u) << (4*kt+2)
                    | ((b1.y >= 0.1f) ? 1u : 0u) << (4*kt+3);
            }
            uint4 AH = ldm4(Qh + aoff + kt*32);
            uint4 AL = ldm4(Ql + aoff + kt*32);
            uint4 kb[8];
#pragma unroll
            for (int np = 0; np < 8; np++) kb[np] = ldm4(Kh + boff + np*4352 + kt*32);
            // pass 1: Qh * Kh
#pragma unroll
            for (int np = 0; np < 8; np++) {
                mmaA(c[2*np], AH, kb[np].x, kb[np].y);
                mmaA(c[2*np+1], AH, kb[np].z, kb[np].w);
            }
            // pass 2: Ql * Kh (reg-cached frags)
#pragma unroll
            for (int np = 0; np < 8; np++) {
                mmaA(c[2*np], AL, kb[np].x, kb[np].y);
                mmaA(c[2*np+1], AL, kb[np].z, kb[np].w);
            }
        }

        CP_WAIT(0);          // V(t) ready
        __syncthreads();     // all warps done reading K(t)
        if (t < 15) {
            tile_load(Kh, g_kh + (size_t)(b*SS + k0 + 128) * HH, HH);
            CP_COMMIT();
        }

        // softmax + dropout(numerator only) + PV — all B frags loaded inline
        // (no vb[] cache: trades +8 ldm4/kt for -32 live registers)
#pragma unroll
        for (int kt = 0; kt < 8; kt++) {
            u32 ph[4], pl[4];
#pragma unroll
            for (int half = 0; half < 2; half++) {
                int n = 2*kt + half;
                int sh = 2*n;
                float p0 = __expf(c[n][0] * SC), p1 = __expf(c[n][1] * SC);
                float p2 = __expf(c[n][2] * SC), p3 = __expf(c[n][3] * SC);
                lsumA += p0 + p1;
                lsumB += p2 + p3;
                p0 *= ((wa >> sh) & 1)     ? INVK : 0.0f;
                p1 *= ((wa >> (sh+1)) & 1) ? INVK : 0.0f;
                p2 *= ((wb >> sh) & 1)     ? INVK : 0.0f;
                p3 *= ((wb >> (sh+1)) & 1) ? INVK : 0.0f;
                ph[2*half]     = packbf(p0, p1);
                pl[2*half]     = packlo(p0, p1, ph[2*half]);
                ph[2*half + 1] = packbf(p2, p3);
                pl[2*half + 1] = packlo(p2, p3, ph[2*half + 1]);
            }
            // pass 1: Ph * Vh (inline)
#pragma unroll
            for (int np = 0; np < 8; np++) {
                uint4 B = ldm4(Vh + boff + np*4352 + kt*32);
                mma16816(o[2*np], ph[0], ph[1], ph[2], ph[3], B.x, B.y);
                mma16816(o[2*np+1], ph[0], ph[1], ph[2], ph[3], B.z, B.w);
            }
            // pass 2: Ph * Vl (inline)
#pragma unroll
            for (int np = 0; np < 8; np++) {
                uint4 B = ldm4(Vl + boff + np*4352 + kt*32);
                mma16816(o[2*np], ph[0], ph[1], ph[2], ph[3], B.x, B.y);
                mma16816(o[2*np+1], ph[0], ph[1], ph[2], ph[3], B.z, B.w);
            }
            // pass 3: Pl * Vh (inline)
#pragma unroll
            for (int np = 0; np < 8; np++) {
                uint4 B = ldm4(Vh + boff + np*4352 + kt*32);
                mma16816(o[2*np], pl[0], pl[1], pl[2], pl[3], B.x, B.y);
                mma16816(o[2*np+1], pl[0], pl[1], pl[2], pl[3], B.z, B.w);
            }
        }
        if (t < 15) CP_WAIT(0);   // K(t+1) ready
        __syncthreads();          // V buffer reuse safety
    }

    // per-row softmax denominators: reduce over quad lanes
#pragma unroll
    for (int off = 1; off <= 2; off <<= 1) {
        lsumA += __shfl_xor_sync(0xffffffffu, lsumA, off);
        lsumB += __shfl_xor_sync(0xffffffffu, lsumB, off);
    }
    const float invA = 1.0f / lsumA, invB = 1.0f / lsumB;

    float* oA = out + ((size_t)(b*SS) + q0 + w*16 + g) * HH;
    float* oB = oA + 8 * HH;
#pragma unroll
    for (int n = 0; n < 16; n++) {
        int col = n*8 + tg*2;
        *(float2*)(oA + col) = make_float2(o[n][0] * invA, o[n][1] * invA);
        *(float2*)(oB + col) = make_float2(o[n][2] * invB, o[n][3] * invB);
    }
}

extern "C" void kernel_launch(void* const* d_in, const int* in_sizes, int n_in,
                              void* d_out, int out_size)
{
    const float* x  = (const float*)d_in[0];
    const float* wq = (const float*)d_in[1];
    const float* wk = (const float*)d_in[2];
    const float* wv = (const float*)d_in[3];
    const float* du = (const float*)d_in[4];
    float* out = (float*)d_out;

    cudaFuncSetAttribute(proj_kernel, cudaFuncAttributeMaxDynamicSharedMemorySize, PROJ_SMEM);
    cudaFuncSetAttribute(attn_kernel, cudaFuncAttributeMaxDynamicSharedMemorySize, ATT_SMEM);

    wprep_kernel<<<48, 256>>>(wq, wk, wv);
    dim3 g1(BB*SS / 128, 2);
    proj_kernel<<<g1, 256, PROJ_SMEM>>>(x);
    dim3 g2(SS / 128, BB);
    attn_kernel<<<g2, 256, ATT_SMEM>>>(du, out);
}

// round 17
// speedup vs baseline: 1.1681x; 1.1525x over previous
#include <cuda_runtime.h>
#include <cuda_bf16.h>

#define BB 8
#define SS 2048
#define EE 1024
#define HH 128

typedef unsigned int u32;

// ---------------- device scratch ----------------
__device__ __nv_bfloat16 g_wth[3][HH*EE], g_wtl[3][HH*EE];   // W^T split [h][e]
__device__ __nv_bfloat16 g_qh[BB*SS*HH];                     // Q hi [s][h]
__device__ __nv_bfloat16 g_kh[BB*SS*HH];                     // K hi [s][h]
__device__ __nv_bfloat16 g_vth[BB*HH*SS], g_vtl[BB*HH*SS];   // V^T [b][h][s]

// ---------------- helpers ----------------
__device__ __forceinline__ u32 smem_u32(const void* p) {
    u32 a;
    asm("{ .reg .u64 t; cvta.to.shared.u64 t, %1; cvt.u32.u64 %0, t; }" : "=r"(a) : "l"(p));
    return a;
}
__device__ __forceinline__ void cpa16(u32 dst, const void* src) {
    asm volatile("cp.async.cg.shared.global [%0], [%1], 16;" :: "r"(dst), "l"(src));
}
#define CP_COMMIT() asm volatile("cp.async.commit_group;" ::: "memory")
#define CP_WAIT(n)  asm volatile("cp.async.wait_group %0;" :: "n"(n) : "memory")

__device__ __forceinline__ u32 packbf(float lo, float hi) {
    u32 r;
    asm("cvt.rn.bf16x2.f32 %0, %1, %2;" : "=r"(r) : "f"(hi), "f"(lo));
    return r;
}
__device__ __forceinline__ u32 packlo(float p0, float p1, u32 h) {
    float r0 = p0 - __uint_as_float(h << 16);
    float r1 = p1 - __uint_as_float(h & 0xffff0000u);
    return packbf(r0, r1);
}
__device__ __forceinline__ void mma16816(float* c, u32 a0, u32 a1, u32 a2, u32 a3,
                                         u32 b0, u32 b1) {
    asm volatile("mma.sync.aligned.m16n8k16.row.col.f32.bf16.bf16.f32 "
                 "{%0,%1,%2,%3},{%4,%5,%6,%7},{%8,%9},{%0,%1,%2,%3};"
                 : "+f"(c[0]), "+f"(c[1]), "+f"(c[2]), "+f"(c[3])
                 : "r"(a0), "r"(a1), "r"(a2), "r"(a3), "r"(b0), "r"(b1));
}
__device__ __forceinline__ void mmaA(float* c, const uint4& a, u32 b0, u32 b1) {
    mma16816(c, a.x, a.y, a.z, a.w, b0, b1);
}
__device__ __forceinline__ uint4 ldm4(u32 addr) {
    uint4 r;
    asm volatile("ldmatrix.sync.aligned.m8n8.x4.shared.b16 {%0,%1,%2,%3}, [%4];"
                 : "=r"(r.x), "=r"(r.y), "=r"(r.z), "=r"(r.w) : "r"(addr));
    return r;
}

// ---------------------------------------------------------------------------
// wprep: W [E][H] f32 -> W^T [H][E] hi/lo bf16, smem-tiled transpose.
// (lo planes still produced for the V projection's W-lo pass.)
// ---------------------------------------------------------------------------
__global__ __launch_bounds__(256) void wprep_kernel(
    const float* __restrict__ wq, const float* __restrict__ wk,
    const float* __restrict__ wv)
{
    __shared__ float Ws[64][132];
    const int m = blockIdx.x >> 4, chunk = blockIdx.x & 15;
    const float* __restrict__ src = (m == 0) ? wq : (m == 1) ? wk : wv;
    const int e0 = chunk * 64;
    const int tid = threadIdx.x;

#pragma unroll
    for (int i = 0; i < 8; i++) {
        int id = tid + i * 256;
        int e = id >> 5, hc = (id & 31) * 4;
        *(float4*)&Ws[e][hc] = *(const float4*)&src[(size_t)(e0 + e) * HH + hc];
    }
    __syncthreads();

    const int h = tid >> 1, eh = (tid & 1) * 32;
    union { __nv_bfloat16 v[32]; uint4 u[4]; } Hh, Ll;
#pragma unroll
    for (int j = 0; j < 32; j++) {
        float f = Ws[eh + j][h];
        __nv_bfloat16 hi = __float2bfloat16_rn(f);
        Hh.v[j] = hi;
        Ll.v[j] = __float2bfloat16_rn(f - __bfloat162float(hi));
    }
    size_t ob = (size_t)h * EE + e0 + eh;
#pragma unroll
    for (int j = 0; j < 4; j++) {
        *(uint4*)&g_wth[m][ob + j*8] = Hh.u[j];
        *(uint4*)&g_wtl[m][ob + j*8] = Ll.u[j];
    }
}

// ---------------------------------------------------------------------------
// proj: 256 thr, warp tile 64x32, fused X f32->bf16 split, cp.async 2-stage.
// blockIdx.y==0: merged q+k CTA, ONE pass per output (Xh*Wqh, Xh*Wkh) —
//   q and k are consumed as bf16-hi in attn, so W-lo compensation is wasted.
//   stage = {Xh, Wqh, Wkh} (3 tiles).
// blockIdx.y==1: v CTA, 3-pass (full split precision — V feeds O directly).
//   stage = {Xh, Xl, Wvh, Wvl} (4 tiles).
// Tiles [128][72] bf16 (144B pitch).
// ---------------------------------------------------------------------------
#define PJ_T 18432            // 128*72*2
#define PROJ_SMEM (2 * 4 * PJ_T)   // 147456 (v CTA's 4-tile stage is the max)

__device__ __forceinline__ void chunk_load(u32 dst, const __nv_bfloat16* src) {
    int tid = threadIdx.x;
#pragma unroll
    for (int i = 0; i < 4; i++) {
        int id = tid + i * 256;
        int r = id >> 3, q = id & 7;
        cpa16(dst + r * 144 + q * 16, (const char*)src + (size_t)r * 2048 + q * 16);
    }
}
__device__ __forceinline__ void ldg_x(float4* xr, const float* __restrict__ x,
                                      int row0, int e0, int r, int half) {
    const float4* s = (const float4*)(x + (size_t)(row0 + r) * EE + e0 + half * 32);
#pragma unroll
    for (int i = 0; i < 8; i++) xr[i] = s[i];
}
__device__ __forceinline__ void conv_store_hi(char* xh_tile, const float4* xr,
                                              int r, int half) {
    const float* f = (const float*)xr;
    u32 h[16];
#pragma unroll
    for (int j = 0; j < 16; j++) h[j] = packbf(f[2*j], f[2*j+1]);
    char* p = xh_tile + r * 144 + half * 64;
#pragma unroll
    for (int q = 0; q < 4; q++)
        *(uint4*)(p + q*16) = make_uint4(h[4*q], h[4*q+1], h[4*q+2], h[4*q+3]);
}
__device__ __forceinline__ void conv_store_hilo(char* xh_tile, char* xl_tile,
                                                const float4* xr, int r, int half) {
    const float* f = (const float*)xr;
    u32 h[16], l[16];
#pragma unroll
    for (int j = 0; j < 16; j++) {
        h[j] = packbf(f[2*j], f[2*j+1]);
        l[j] = packlo(f[2*j], f[2*j+1], h[j]);
    }
    char* p = xh_tile + r * 144 + half * 64;
    char* q2 = xl_tile + r * 144 + half * 64;
#pragma unroll
    for (int q = 0; q < 4; q++) {
        *(uint4*)(p + q*16)  = make_uint4(h[4*q], h[4*q+1], h[4*q+2], h[4*q+3]);
        *(uint4*)(q2 + q*16) = make_uint4(l[4*q], l[4*q+1], l[4*q+2], l[4*q+3]);
    }
}

__global__ __launch_bounds__(256) void proj_kernel(const float* __restrict__ x) {
    extern __shared__ char sm[];
    const u32 sb = smem_u32(sm);
    const int tid = threadIdx.x, w = tid >> 5, lane = tid & 31;
    const int wy = w >> 2, wx = w & 3;
    const int g = lane >> 2, tg = lane & 3;
    const int row0 = blockIdx.x * 128;
    const bool isqk = (blockIdx.y == 0);
    const int xr_r = tid >> 1, xr_half = tid & 1;

    const u32 aoff = (u32)((wy*64 + (lane & 15)) * 144 + ((lane >> 4) & 1) * 16);
    const u32 boff = (u32)((wx*32 + (lane & 7) + ((lane >> 4) & 1) * 8) * 144
                           + ((lane >> 3) & 1) * 16);

    float c0[16][4], c1[16][4];
#pragma unroll
    for (int n = 0; n < 16; n++)
#pragma unroll
        for (int j = 0; j < 4; j++) { c0[n][j] = 0.0f; c1[n][j] = 0.0f; }

    const u32 STG = (isqk ? 3u : 4u) * PJ_T;

    float4 xr[8];
    ldg_x(xr, x, row0, 0, xr_r, xr_half);
    if (isqk) {
        conv_store_hi(sm, xr, xr_r, xr_half);
        chunk_load(sb + PJ_T,   g_wth[0]);
        chunk_load(sb + 2*PJ_T, g_wth[1]);
    } else {
        conv_store_hilo(sm, sm + PJ_T, xr, xr_r, xr_half);
        chunk_load(sb + 2*PJ_T, g_wth[2]);
        chunk_load(sb + 3*PJ_T, g_wtl[2]);
    }
    CP_COMMIT();
    ldg_x(xr, x, row0, 64, xr_r, xr_half);

    for (int ch = 0; ch < 16; ch++) {
        int cur = ch & 1;
        if (ch < 15) {
            char* np = sm + (cur ^ 1) * STG;
            u32 nb = sb + (cur ^ 1) * STG;
            int o = (ch + 1) * 64;
            if (isqk) {
                chunk_load(nb + PJ_T,   g_wth[0] + o);
                chunk_load(nb + 2*PJ_T, g_wth[1] + o);
            } else {
                chunk_load(nb + 2*PJ_T, g_wth[2] + o);
                chunk_load(nb + 3*PJ_T, g_wtl[2] + o);
            }
            CP_COMMIT();
            if (isqk) conv_store_hi(np, xr, xr_r, xr_half);
            else      conv_store_hilo(np, np + PJ_T, xr, xr_r, xr_half);
            if (ch < 14) ldg_x(xr, x, row0, (ch + 2) * 64, xr_r, xr_half);
            CP_WAIT(1);
        } else {
            CP_WAIT(0);
        }
        __syncthreads();
        const u32 base = sb + cur * STG;

        if (isqk) {
#pragma unroll
            for (int kt = 0; kt < 4; kt++) {
                uint4 A[4];
#pragma unroll
                for (int mf = 0; mf < 4; mf++)
                    A[mf] = ldm4(base + aoff + mf*2304 + kt*32);
                // pass: q = Xh * Wqh
                {
                    uint4 B0 = ldm4(base + PJ_T + boff + kt*32);
                    uint4 B1 = ldm4(base + PJ_T + boff + 2304 + kt*32);
#pragma unroll
                    for (int mf = 0; mf < 4; mf++) {
                        mmaA(c0[mf*4+0], A[mf], B0.x, B0.y);
                        mmaA(c0[mf*4+1], A[mf], B0.z, B0.w);
                        mmaA(c0[mf*4+2], A[mf], B1.x, B1.y);
                        mmaA(c0[mf*4+3], A[mf], B1.z, B1.w);
                    }
                }
                // pass: k = Xh * Wkh
                {
                    uint4 B0 = ldm4(base + 2*PJ_T + boff + kt*32);
                    uint4 B1 = ldm4(base + 2*PJ_T + boff + 2304 + kt*32);
#pragma unroll
                    for (int mf = 0; mf < 4; mf++) {
                        mmaA(c1[mf*4+0], A[mf], B0.x, B0.y);
                        mmaA(c1[mf*4+1], A[mf], B0.z, B0.w);
                        mmaA(c1[mf*4+2], A[mf], B1.x, B1.y);
                        mmaA(c1[mf*4+3], A[mf], B1.z, B1.w);
                    }
                }
            }
        } else {
#pragma unroll
            for (int kt = 0; kt < 4; kt++) {
                uint4 A[4], AL[4];
#pragma unroll
                for (int mf = 0; mf < 4; mf++) {
                    A[mf]  = ldm4(base + aoff + mf*2304 + kt*32);
                    AL[mf] = ldm4(base + PJ_T + aoff + mf*2304 + kt*32);
                }
                uint4 Bh0 = ldm4(base + 2*PJ_T + boff + kt*32);
                uint4 Bh1 = ldm4(base + 2*PJ_T + boff + 2304 + kt*32);
                uint4 Bl0 = ldm4(base + 3*PJ_T + boff + kt*32);
                uint4 Bl1 = ldm4(base + 3*PJ_T + boff + 2304 + kt*32);
#pragma unroll
                for (int mf = 0; mf < 4; mf++) {
                    mmaA(c0[mf*4+0], A[mf], Bh0.x, Bh0.y);
                    mmaA(c0[mf*4+1], A[mf], Bh0.z, Bh0.w);
                    mmaA(c0[mf*4+2], A[mf], Bh1.x, Bh1.y);
                    mmaA(c0[mf*4+3], A[mf], Bh1.z, Bh1.w);
                }
#pragma unroll
                for (int mf = 0; mf < 4; mf++) {
                    mmaA(c0[mf*4+0], A[mf], Bl0.x, Bl0.y);
                    mmaA(c0[mf*4+1], A[mf], Bl0.z, Bl0.w);
                    mmaA(c0[mf*4+2], A[mf], Bl1.x, Bl1.y);
                    mmaA(c0[mf*4+3], A[mf], Bl1.z, Bl1.w);
                }
#pragma unroll
                for (int mf = 0; mf < 4; mf++) {
                    mmaA(c0[mf*4+0], AL[mf], Bh0.x, Bh0.y);
                    mmaA(c0[mf*4+1], AL[mf], Bh0.z, Bh0.w);
                    mmaA(c0[mf*4+2], AL[mf], Bh1.x, Bh1.y);
                    mmaA(c0[mf*4+3], AL[mf], Bh1.z, Bh1.w);
                }
            }
        }
        __syncthreads();
    }

    if (isqk) {
#pragma unroll
        for (int mf = 0; mf < 4; mf++) {
            size_t rA = (size_t)(row0 + wy*64 + mf*16 + g) * HH;
            size_t rB = rA + 8 * HH;
#pragma unroll
            for (int f = 0; f < 4; f++) {
                int col = wx*32 + (f >> 1)*16 + (f & 1)*8 + tg*2;
                const float* cq = c0[mf*4 + f];
                const float* ck = c1[mf*4 + f];
                *(u32*)&g_qh[rA + col] = packbf(cq[0], cq[1]);
                *(u32*)&g_qh[rB + col] = packbf(cq[2], cq[3]);
                *(u32*)&g_kh[rA + col] = packbf(ck[0], ck[1]);
                *(u32*)&g_kh[rB + col] = packbf(ck[2], ck[3]);
            }
        }
    } else {
        float* Cs = (float*)sm;   // [128][132]
#pragma unroll
        for (int mf = 0; mf < 4; mf++) {
            int r = wy*64 + mf*16 + g;
#pragma unroll
            for (int f = 0; f < 4; f++) {
                int col = wx*32 + (f >> 1)*16 + (f & 1)*8 + tg*2;
                const float* cv = c0[mf*4 + f];
                Cs[r * 132 + col]           = cv[0];
                Cs[r * 132 + col + 1]       = cv[1];
                Cs[(r + 8) * 132 + col]     = cv[2];
                Cs[(r + 8) * 132 + col + 1] = cv[3];
            }
        }
        __syncthreads();
        int h = tid >> 1, half = tid & 1;
        int b = row0 >> 11, s0 = row0 & 2047;
        union { __nv_bfloat16 v[64]; uint4 u[8]; } Hh, Ll;
#pragma unroll
        for (int j = 0; j < 64; j++) {
            float f = Cs[(half*64 + j) * 132 + h];
            __nv_bfloat16 hi = __float2bfloat16_rn(f);
            Hh.v[j] = hi;
            Ll.v[j] = __float2bfloat16_rn(f - __bfloat162float(hi));
        }
        size_t ob = ((size_t)(b*HH + h)) * SS + s0 + half*64;
#pragma unroll
        for (int j = 0; j < 8; j++) {
            *(uint4*)&g_vth[ob + j*8] = Hh.u[j];
            *(uint4*)&g_vtl[ob + j*8] = Ll.u[j];
        }
    }
}

// ---------------------------------------------------------------------------
// attn (R11 loop structure, Q bf16-hi): CTA = 128 Q rows x one batch,
// 256 threads, 8 warps, monolithic 128-key tiles. QK 1-pass (Qh*Kh).
// PV 3-pass with Vh frags reg-cached (the proven-fastest PV form).
// Dropout bits built in-loop. smem: Qh,Kh,Vth,Vtl [128][136] (272B pitch).
// ---------------------------------------------------------------------------
#define AT_T 34816            // 128*136*2
#define ATT_SMEM (4 * AT_T)   // 139264

__device__ __forceinline__ void tile_load(u32 dst, const __nv_bfloat16* src,
                                          int stride_elems) {
    int tid = threadIdx.x;
#pragma unroll
    for (int i = 0; i < 8; i++) {
        int id = tid + i * 256;
        int r = id >> 4, q = id & 15;
        cpa16(dst + r * 272 + q * 16,
              (const char*)src + (size_t)r * stride_elems * 2 + q * 16);
    }
}

__global__ __launch_bounds__(256) void attn_kernel(
    const float* __restrict__ du_g, float* __restrict__ out)
{
    extern __shared__ char sm[];
    const u32 sb = smem_u32(sm);
    const int tid = threadIdx.x, w = tid >> 5, lane = tid & 31;
    const int g = lane >> 2, tg = lane & 3;
    const int b = blockIdx.y;
    const int q0 = blockIdx.x * 128;

    const u32 Qh = sb, Kh = sb + AT_T;
    const u32 Vh = sb + 2*AT_T, Vl = sb + 3*AT_T;

    const u32 aoff = (u32)((w*16 + (lane & 15)) * 272 + ((lane >> 4) & 1) * 16);
    const u32 boff = (u32)(((lane & 7) + ((lane >> 4) & 1) * 8) * 272 + ((lane >> 3) & 1) * 16);

    const size_t qoff = (size_t)(b*SS + q0) * HH;
    tile_load(Qh, g_qh + qoff, HH);
    tile_load(Kh, g_kh + (size_t)(b*SS) * HH, HH);
    CP_COMMIT();

    float o[16][4];
#pragma unroll
    for (int n = 0; n < 16; n++)
#pragma unroll
        for (int j = 0; j < 4; j++) o[n][j] = 0.0f;
    float lsumA = 0.0f, lsumB = 0.0f;

    const float SC = 0.03125f;        // 1024^-0.5
    const float INVK = 1.0f / 0.9f;
    const float* duA = du_g + ((size_t)(b*SS) + q0 + w*16 + g) * SS;
    const float* duB = duA + 8 * SS;

    CP_WAIT(0);
    __syncthreads();

    for (int t = 0; t < 16; t++) {
        const int k0 = t * 128;
        // V(t) load overlaps QK(t)
        tile_load(Vh, g_vth + (size_t)(b*HH) * SS + k0, SS);
        tile_load(Vl, g_vtl + (size_t)(b*HH) * SS + k0, SS);
        CP_COMMIT();

        float c[16][4];
#pragma unroll
        for (int n = 0; n < 16; n++)
#pragma unroll
            for (int j = 0; j < 4; j++) c[n][j] = 0.0f;

        // dropout keep-bits: bit 2n -> key col n*8+tg*2
        u32 wa = 0, wb = 0;

#pragma unroll
        for (int kt = 0; kt < 8; kt++) {
            {
                float2 a0 = *(const float2*)(duA + k0 + kt*16 + tg*2);
                float2 a1 = *(const float2*)(duA + k0 + kt*16 + 8 + tg*2);
                float2 b0 = *(const float2*)(duB + k0 + kt*16 + tg*2);
                float2 b1 = *(const float2*)(duB + k0 + kt*16 + 8 + tg*2);
                wa |= ((a0.x >= 0.1f) ? 1u : 0u) << (4*kt)
                    | ((a0.y >= 0.1f) ? 1u : 0u) << (4*kt+1)
                    | ((a1.x >= 0.1f) ? 1u : 0u) << (4*kt+2)
                    | ((a1.y >= 0.1f) ? 1u : 0u) << (4*kt+3);
                wb |= ((b0.x >= 0.1f) ? 1u : 0u) << (4*kt)
                    | ((b0.y >= 0.1f) ? 1u : 0u) << (4*kt+1)
                    | ((b1.x >= 0.1f) ? 1u : 0u) << (4*kt+2)
                    | ((b1.y >= 0.1f) ? 1u : 0u) << (4*kt+3);
            }
            uint4 AH = ldm4(Qh + aoff + kt*32);
            // single pass: Qh * Kh
#pragma unroll
            for (int np = 0; np < 8; np++) {
                uint4 B = ldm4(Kh + boff + np*4352 + kt*32);
                mmaA(c[2*np], AH, B.x, B.y);
                mmaA(c[2*np+1], AH, B.z, B.w);
            }
        }

        CP_WAIT(0);          // V(t) ready
        __syncthreads();     // all warps done reading K(t)
        if (t < 15) {
            tile_load(Kh, g_kh + (size_t)(b*SS + k0 + 128) * HH, HH);
            CP_COMMIT();
        }

        // softmax + dropout(numerator only) + PV
#pragma unroll
        for (int kt = 0; kt < 8; kt++) {
            u32 ph[4], pl[4];
#pragma unroll
            for (int half = 0; half < 2; half++) {
                int n = 2*kt + half;
                int sh = 2*n;
                float p0 = __expf(c[n][0] * SC), p1 = __expf(c[n][1] * SC);
                float p2 = __expf(c[n][2] * SC), p3 = __expf(c[n][3] * SC);
                lsumA += p0 + p1;
                lsumB += p2 + p3;
                p0 *= ((wa >> sh) & 1)     ? INVK : 0.0f;
                p1 *= ((wa >> (sh+1)) & 1) ? INVK : 0.0f;
                p2 *= ((wb >> sh) & 1)     ? INVK : 0.0f;
                p3 *= ((wb >> (sh+1)) & 1) ? INVK : 0.0f;
                ph[2*half]     = packbf(p0, p1);
                pl[2*half]     = packlo(p0, p1, ph[2*half]);
                ph[2*half + 1] = packbf(p2, p3);
                pl[2*half + 1] = packlo(p2, p3, ph[2*half + 1]);
            }
            uint4 vb[8];
#pragma unroll
            for (int np = 0; np < 8; np++) vb[np] = ldm4(Vh + boff + np*4352 + kt*32);
            // pass 1: Ph * Vh (cached frags)
#pragma unroll
            for (int np = 0; np < 8; np++) {
                mma16816(o[2*np], ph[0], ph[1], ph[2], ph[3], vb[np].x, vb[np].y);
                mma16816(o[2*np+1], ph[0], ph[1], ph[2], ph[3], vb[np].z, vb[np].w);
            }
            // pass 2: Ph * Vl (inline loads)
#pragma unroll
            for (int np = 0; np < 8; np++) {
                uint4 B = ldm4(Vl + boff + np*4352 + kt*32);
                mma16816(o[2*np], ph[0], ph[1], ph[2], ph[3], B.x, B.y);
                mma16816(o[2*np+1], ph[0], ph[1], ph[2], ph[3], B.z, B.w);
            }
            // pass 3: Pl * Vh (reg-cached frags)
#pragma unroll
            for (int np = 0; np < 8; np++) {
                mma16816(o[2*np], pl[0], pl[1], pl[2], pl[3], vb[np].x, vb[np].y);
                mma16816(o[2*np+1], pl[0], pl[1], pl[2], pl[3], vb[np].z, vb[np].w);
            }
        }
        if (t < 15) CP_WAIT(0);   // K(t+1) ready
        __syncthreads();          // V buffer reuse safety
    }

    // per-row softmax denominators: reduce over quad lanes
#pragma unroll
    for (int off = 1; off <= 2; off <<= 1) {
        lsumA += __shfl_xor_sync(0xffffffffu, lsumA, off);
        lsumB += __shfl_xor_sync(0xffffffffu, lsumB, off);
    }
    const float invA = 1.0f / lsumA, invB = 1.0f / lsumB;

    float* oA = out + ((size_t)(b*SS) + q0 + w*16 + g) * HH;
    float* oB = oA + 8 * HH;
#pragma unroll
    for (int n = 0; n < 16; n++) {
        int col = n*8 + tg*2;
        *(float2*)(oA + col) = make_float2(o[n][0] * invA, o[n][1] * invA);
        *(float2*)(oB + col) = make_float2(o[n][2] * invB, o[n][3] * invB);
    }
}

extern "C" void kernel_launch(void* const* d_in, const int* in_sizes, int n_in,
                              void* d_out, int out_size)
{
    const float* x  = (const float*)d_in[0];
    const float* wq = (const float*)d_in[1];
    const float* wk = (const float*)d_in[2];
    const float* wv = (const float*)d_in[3];
    const float* du = (const float*)d_in[4];
    float* out = (float*)d_out;

    cudaFuncSetAttribute(proj_kernel, cudaFuncAttributeMaxDynamicSharedMemorySize, PROJ_SMEM);
    cudaFuncSetAttribute(attn_kernel, cudaFuncAttributeMaxDynamicSharedMemorySize, ATT_SMEM);

    wprep_kernel<<<48, 256>>>(wq, wk, wv);
    dim3 g1(BB*SS / 128, 2);
    proj_kernel<<<g1, 256, PROJ_SMEM>>>(x);
    dim3 g2(SS / 128, BB);
    attn_kernel<<<g2, 256, ATT_SMEM>>>(du, out);
}